// round 10
// baseline (speedup 1.0000x reference)
#include <cuda_runtime.h>
#include <cuda_bf16.h>
#include <cstdint>
#include <math.h>

#define D 128
#define NU_MAX 100000
#define NI_MAX 50000
#define E_MAX  500000

// ---------------- scratch (device globals; no allocation allowed) ----------------
__device__ float4 g_agg_user4[(size_t)NU_MAX * D / 4];
__device__ float4 g_agg_item4[(size_t)NI_MAX * D / 4];
__device__ float  g_deg_user[NU_MAX];
__device__ float  g_deg_item[NI_MAX];
// pre-split, pre-swizzled bf16 weights: tiles m = {W1hi, W1lo, W2hi, W2lo},
// each [128 n-rows][128 k] bf16, row = 256B, chunk (16B) swizzled by (n&7). 32KB/tile.
__device__ unsigned char g_wt[4 * 32768];
// bucket-CSR build scratch: node index space = [0,NI) items, [NI, NI+NU) users
__device__ int   g_cnt[NU_MAX + NI_MAX];
__device__ int   g_base[NU_MAX + NI_MAX];
__device__ int   g_wr[NU_MAX + NI_MAX];
__device__ int   g_cursor[2];
__device__ uint2 g_epack_u2i[E_MAX];   // (src_user, norm_bits), grouped by dst item
__device__ uint2 g_epack_i2u[E_MAX];   // (src_item, norm_bits), grouped by dst user

// ---------------- helpers ----------------
__device__ __forceinline__ uint32_t smem_u32(const void* p) {
    uint32_t a;
    asm("{ .reg .u64 t; cvta.to.shared.u64 t, %1; cvt.u32.u64 %0, t; }" : "=r"(a) : "l"(p));
    return a;
}
__device__ __forceinline__ void ldmx4(uint32_t* r, uint32_t addr) {
    asm volatile("ldmatrix.sync.aligned.m8n8.x4.shared.b16 {%0,%1,%2,%3}, [%4];"
                 : "=r"(r[0]), "=r"(r[1]), "=r"(r[2]), "=r"(r[3]) : "r"(addr));
}
__device__ __forceinline__ void mma16816(float* c, const uint32_t* a, uint32_t b0, uint32_t b1) {
    asm volatile("mma.sync.aligned.m16n8k16.row.col.f32.bf16.bf16.f32 "
                 "{%0,%1,%2,%3}, {%4,%5,%6,%7}, {%8,%9}, {%0,%1,%2,%3};"
                 : "+f"(c[0]), "+f"(c[1]), "+f"(c[2]), "+f"(c[3])
                 : "r"(a[0]), "r"(a[1]), "r"(a[2]), "r"(a[3]), "r"(b0), "r"(b1));
}
__device__ __forceinline__ void pack_hl(const float* v, uint4* hi, uint4* lo) {
    uint32_t h[4], l[4];
    #pragma unroll
    for (int i = 0; i < 4; ++i) {
        float2 p = make_float2(v[2 * i], v[2 * i + 1]);
        __nv_bfloat162 hb = __float22bfloat162_rn(p);
        float2 r = make_float2(p.x - __bfloat162float(hb.x),
                               p.y - __bfloat162float(hb.y));
        __nv_bfloat162 lb = __float22bfloat162_rn(r);
        h[i] = *(uint32_t*)&hb;
        l[i] = *(uint32_t*)&lb;
    }
    *hi = make_uint4(h[0], h[1], h[2], h[3]);
    *lo = make_uint4(l[0], l[1], l[2], l[3]);
}

// ---------------- build phase ----------------
__global__ void zero_cnt_kernel(int total_nodes) {
    int i = blockIdx.x * blockDim.x + threadIdx.x;
    if (i < total_nodes) g_cnt[i] = 0;
    if (i < 2) g_cursor[i] = 0;
}

__global__ void count_kernel(const int* __restrict__ dst_u2i,
                             const int* __restrict__ dst_i2u, int E, int NI) {
    int i = blockIdx.x * blockDim.x + threadIdx.x;
    if (i < E) {
        atomicAdd(&g_cnt[__ldg(dst_u2i + i)], 1);
    } else if (i < 2 * E) {
        atomicAdd(&g_cnt[NI + __ldg(dst_i2u + (i - E))], 1);
    }
}

__global__ void base_kernel(int total_nodes, int NI) {
    int i = blockIdx.x * blockDim.x + threadIdx.x;
    if (i >= total_nodes) return;
    int c = g_cnt[i];
    int b = atomicAdd(&g_cursor[i < NI ? 0 : 1], c);
    g_base[i] = b;
    g_wr[i] = b;
}

__global__ void fill_kernel(const int* __restrict__ src_u2i,
                            const int* __restrict__ dst_u2i,
                            const float* __restrict__ norm_u2i,
                            const int* __restrict__ src_i2u,
                            const int* __restrict__ dst_i2u,
                            const float* __restrict__ norm_i2u,
                            int E, int NI) {
    int i = blockIdx.x * blockDim.x + threadIdx.x;
    if (i < E) {
        int d = __ldg(dst_u2i + i);
        int p = atomicAdd(&g_wr[d], 1);
        if (p < E_MAX)
            g_epack_u2i[p] = make_uint2((uint32_t)__ldg(src_u2i + i),
                                        __float_as_uint(__ldg(norm_u2i + i)));
    } else if (i < 2 * E) {
        int j = i - E;
        int d = __ldg(dst_i2u + j);
        int p = atomicAdd(&g_wr[NI + d], 1);
        if (p < E_MAX)
            g_epack_i2u[p] = make_uint2((uint32_t)__ldg(src_i2u + j),
                                        __float_as_uint(__ldg(norm_i2u + j)));
    }
}

// ---------------- gather: one warp per dst node, no atomics, no pre-zero ----------------
__global__ void gather_kernel(const float* __restrict__ feat_user,
                              const float* __restrict__ feat_item,
                              int NU, int NI) {
    int gw = (blockIdx.x * blockDim.x + threadIdx.x) >> 5;
    int lane = threadIdx.x & 31;
    int total = NI + NU;
    if (gw >= total) return;

    const bool is_item = gw < NI;
    const int node = is_item ? gw : gw - NI;
    const float* fs = is_item ? feat_user : feat_item;
    const uint2* ep = is_item ? g_epack_u2i : g_epack_i2u;
    float4* agg = is_item ? (g_agg_item4 + (size_t)node * 32)
                          : (g_agg_user4 + (size_t)node * 32);
    float* degp = is_item ? (g_deg_item + node) : (g_deg_user + node);

    int e  = __ldg(g_base + gw);
    int e1 = e + __ldg(g_cnt + gw);

    float4 acc = make_float4(0.f, 0.f, 0.f, 0.f);
    float dg = 0.f;
    uint2 pk;
    float4 f;
    if (e < e1) {
        pk = __ldg(ep + e);
        f = __ldg(((const float4*)(fs + (size_t)pk.x * D)) + lane);
    }
    while (e < e1) {
        float w = __uint_as_float(pk.y);
        float4 cf = f;
        ++e;
        if (e < e1) {
            pk = __ldg(ep + e);
            f = __ldg(((const float4*)(fs + (size_t)pk.x * D)) + lane);
        }
        acc.x += w * cf.x;
        acc.y += w * cf.y;
        acc.z += w * cf.z;
        acc.w += w * cf.w;
        dg += w;
    }
    agg[lane] = acc;
    if (lane == 0) *degp = dg;
}

// ---------------- weight prep: bf16 hi/lo split, swizzled n-major tiles ----------------
__global__ void wprep_kernel(const float* __restrict__ W1, const float* __restrict__ W2) {
    int idx = blockIdx.x * blockDim.x + threadIdx.x;
    if (idx >= 2 * D * D) return;
    int w = idx >> 14;
    int k = (idx >> 7) & 127;
    int n = idx & 127;
    float v = __ldg((w ? W2 : W1) + k * D + n);
    __nv_bfloat16 hb = __float2bfloat16(v);
    __nv_bfloat16 lb = __float2bfloat16(v - __bfloat162float(hb));
    uint32_t off = (uint32_t)(n * 256 + (((k >> 3) ^ (n & 7)) * 16) + (k & 7) * 2);
    *(__nv_bfloat16*)(g_wt + (2 * w + 0) * 32768 + off) = hb;
    *(__nv_bfloat16*)(g_wt + (2 * w + 1) * 32768 + off) = lb;
}

// ---------------- mma.sync fused dual-GEMM + bias + LeakyReLU + row L2-normalize ----------------
#define SM_W_OFF 131072
#define SM_TOTAL (131072 + 65536)

__global__ __launch_bounds__(256, 1)
void gemm_mma_kernel(const float* __restrict__ feat_user,
                     const float* __restrict__ feat_item,
                     const float* __restrict__ b1v,
                     const float* __restrict__ b2v,
                     float* __restrict__ out,
                     int NU, int NI, int ublocks) {
    extern __shared__ char smem[];
    const uint32_t sbase = smem_u32(smem);
    const int tid = threadIdx.x;
    const int wid = tid >> 5;
    const int lane = tid & 31;

    const bool is_user = (int)blockIdx.x < ublocks;
    const int bx = is_user ? blockIdx.x : blockIdx.x - ublocks;
    const int Nrows = is_user ? NU : NI;
    const int row0 = bx * 128;
    const float* feat = is_user ? feat_user : feat_item;
    const float* agg  = is_user ? (const float*)g_agg_user4 : (const float*)g_agg_item4;
    const float* deg  = is_user ? g_deg_user : g_deg_item;
    float* outp = is_user ? out : out + (size_t)NU * D;

    // ---- stage A-operand tiles ----
    {
        int r = tid >> 1, khalf = tid & 1;
        int grow = row0 + r;
        bool valid = grow < Nrows;
        const float4* fp = (const float4*)(feat + (size_t)grow * D) + khalf * 16;
        const float4* ap = (const float4*)(agg  + (size_t)grow * D) + khalf * 16;
        const float4 z = make_float4(0.f, 0.f, 0.f, 0.f);
        uint32_t rbase = (uint32_t)(r * 256);
        int rs = r & 7;
        #pragma unroll
        for (int j = 0; j < 8; ++j) {
            float4 f0 = valid ? __ldg(fp + 2 * j)     : z;
            float4 f1 = valid ? __ldg(fp + 2 * j + 1) : z;
            float4 a0 = valid ? __ldg(ap + 2 * j)     : z;
            float4 a1 = valid ? __ldg(ap + 2 * j + 1) : z;
            float Av[8] = {f0.x + a0.x, f0.y + a0.y, f0.z + a0.z, f0.w + a0.w,
                           f1.x + a1.x, f1.y + a1.y, f1.z + a1.z, f1.w + a1.w};
            float Bv[8] = {f0.x * a0.x, f0.y * a0.y, f0.z * a0.z, f0.w * a0.w,
                           f1.x * a1.x, f1.y * a1.y, f1.z * a1.z, f1.w * a1.w};
            uint32_t off = rbase + (uint32_t)((((khalf * 8 + j) ^ rs)) * 16);
            uint4 hi, lo;
            pack_hl(Av, &hi, &lo);
            *(uint4*)(smem + 0 * 32768 + off) = hi;
            *(uint4*)(smem + 1 * 32768 + off) = lo;
            pack_hl(Bv, &hi, &lo);
            *(uint4*)(smem + 2 * 32768 + off) = hi;
            *(uint4*)(smem + 3 * 32768 + off) = lo;
        }
    }

    const int rg = wid & 3;
    const int cg = wid >> 2;
    const int lrow = lane & 15;
    const int lkh = lane >> 4;
    const int lswz = lrow & 7;

    float acc[2][2][4][4];
    #pragma unroll
    for (int h = 0; h < 2; ++h)
        #pragma unroll
        for (int mb = 0; mb < 2; ++mb)
            #pragma unroll
            for (int nb = 0; nb < 4; ++nb)
                #pragma unroll
                for (int e = 0; e < 4; ++e) acc[h][mb][nb][e] = 0.f;

    const int aidx[6] = {0, 0, 1, 2, 2, 3};
    const int widx[6] = {0, 1, 0, 2, 3, 2};

    const uint32_t rowA0 = (uint32_t)((rg * 32 + lrow) * 256);
    const uint32_t rowA1 = rowA0 + 16 * 256;
    const uint32_t rowB0 = (uint32_t)((cg * 32 + lrow) * 256);
    const uint32_t rowB1 = rowB0 + 16 * 256;

    for (int h = 0; h < 2; ++h) {
        __syncthreads();
        #pragma unroll
        for (int m = 0; m < 4; ++m) {
            const uint4* src = (const uint4*)(g_wt + m * 32768 + h * 16384);
            uint4* dst = (uint4*)(smem + SM_W_OFF + m * 16384);
            #pragma unroll
            for (int t = tid; t < 1024; t += 256) dst[t] = __ldg(src + t);
        }
        __syncthreads();

        #pragma unroll
        for (int p = 0; p < 6; ++p) {
            const uint32_t abase = sbase + (uint32_t)(aidx[p] * 32768);
            const uint32_t wbase = sbase + SM_W_OFF + (uint32_t)(widx[p] * 16384);
            #pragma unroll
            for (int ks = 0; ks < 8; ++ks) {
                uint32_t coff = (uint32_t)(((ks * 2 + lkh) ^ lswz) * 16);
                uint32_t a0r[4], a1r[4], b0r[4], b1r[4];
                ldmx4(a0r, abase + rowA0 + coff);
                ldmx4(a1r, abase + rowA1 + coff);
                ldmx4(b0r, wbase + rowB0 + coff);
                ldmx4(b1r, wbase + rowB1 + coff);
                #pragma unroll
                for (int mb = 0; mb < 2; ++mb) {
                    const uint32_t* a = mb ? a1r : a0r;
                    mma16816(acc[h][mb][0], a, b0r[0], b0r[2]);
                    mma16816(acc[h][mb][1], a, b0r[1], b0r[3]);
                    mma16816(acc[h][mb][2], a, b1r[0], b1r[2]);
                    mma16816(acc[h][mb][3], a, b1r[1], b1r[3]);
                }
            }
        }
    }
    __syncthreads();

    // ---- epilogue ----
    const int rl = lane >> 2;
    float dg[2][2], ss[2][2];
    #pragma unroll
    for (int mb = 0; mb < 2; ++mb)
        #pragma unroll
        for (int rh = 0; rh < 2; ++rh) {
            int grow = row0 + rg * 32 + mb * 16 + rh * 8 + rl;
            dg[mb][rh] = (grow < Nrows) ? __ldg(deg + grow) : 0.f;
            ss[mb][rh] = 0.f;
        }

    #pragma unroll
    for (int h = 0; h < 2; ++h)
        #pragma unroll
        for (int nb = 0; nb < 4; ++nb) {
            int col = h * 64 + cg * 32 + nb * 8 + (lane & 3) * 2;
            float2 bb1 = __ldg((const float2*)(b1v + col));
            float2 bb2 = __ldg((const float2*)(b2v + col));
            #pragma unroll
            for (int mb = 0; mb < 2; ++mb)
                #pragma unroll
                for (int rh = 0; rh < 2; ++rh) {
                    float d = dg[mb][rh];
                    float* c = acc[h][mb][nb] + rh * 2;
                    float h0 = c[0] + (1.f + d) * bb1.x + d * bb2.x;
                    float h1 = c[1] + (1.f + d) * bb1.y + d * bb2.y;
                    h0 = (h0 > 0.f) ? h0 : 0.2f * h0;
                    h1 = (h1 > 0.f) ? h1 : 0.2f * h1;
                    c[0] = h0; c[1] = h1;
                    ss[mb][rh] += h0 * h0 + h1 * h1;
                }
        }
    #pragma unroll
    for (int off = 1; off <= 2; off <<= 1)
        #pragma unroll
        for (int mb = 0; mb < 2; ++mb)
            #pragma unroll
            for (int rh = 0; rh < 2; ++rh)
                ss[mb][rh] += __shfl_xor_sync(0xffffffffu, ss[mb][rh], off);

    float* part = (float*)smem;
    if ((lane & 3) == 0) {
        #pragma unroll
        for (int mb = 0; mb < 2; ++mb)
            #pragma unroll
            for (int rh = 0; rh < 2; ++rh)
                part[cg * 128 + rg * 32 + mb * 16 + rh * 8 + rl] = ss[mb][rh];
    }
    __syncthreads();

    #pragma unroll
    for (int mb = 0; mb < 2; ++mb)
        #pragma unroll
        for (int rh = 0; rh < 2; ++rh) {
            int lrow128 = rg * 32 + mb * 16 + rh * 8 + rl;
            int grow = row0 + lrow128;
            float tot = ss[mb][rh] + part[(1 ^ cg) * 128 + lrow128];
            float inv = 1.f / fmaxf(sqrtf(tot), 1e-12f);
            if (grow < Nrows) {
                #pragma unroll
                for (int h = 0; h < 2; ++h)
                    #pragma unroll
                    for (int nb = 0; nb < 4; ++nb) {
                        int col = h * 64 + cg * 32 + nb * 8 + (lane & 3) * 2;
                        float* c = acc[h][mb][nb] + rh * 2;
                        *(float2*)(outp + (size_t)grow * D + col) =
                            make_float2(c[0] * inv, c[1] * inv);
                    }
            }
        }
}

// ---------------- launch ----------------
extern "C" void kernel_launch(void* const* d_in, const int* in_sizes, int n_in,
                              void* d_out, int out_size) {
    const float* feat_user = (const float*)d_in[0];
    const float* feat_item = (const float*)d_in[1];
    const float* W1        = (const float*)d_in[2];
    const float* b1        = (const float*)d_in[3];
    const float* W2        = (const float*)d_in[4];
    const float* b2        = (const float*)d_in[5];
    const float* norm_u2i  = (const float*)d_in[6];
    const float* norm_i2u  = (const float*)d_in[7];
    const int*   e_ui_src  = (const int*)d_in[8];
    const int*   e_ui_dst  = (const int*)d_in[9];
    const int*   e_iu_src  = (const int*)d_in[10];
    const int*   e_iu_dst  = (const int*)d_in[11];
    float* out = (float*)d_out;

    const int NU = in_sizes[0] / D;
    const int NI = in_sizes[1] / D;
    const int E  = in_sizes[8];
    const int total_nodes = NU + NI;

    cudaFuncSetAttribute((const void*)gemm_mma_kernel,
                         cudaFuncAttributeMaxDynamicSharedMemorySize, SM_TOTAL);

    zero_cnt_kernel<<<(total_nodes + 255) / 256, 256>>>(total_nodes);
    wprep_kernel<<<(2 * D * D + 255) / 256, 256>>>(W1, W2);
    count_kernel<<<(2 * E + 255) / 256, 256>>>(e_ui_dst, e_iu_dst, E, NI);
    base_kernel<<<(total_nodes + 255) / 256, 256>>>(total_nodes, NI);
    fill_kernel<<<(2 * E + 255) / 256, 256>>>(e_ui_src, e_ui_dst, norm_u2i,
                                              e_iu_src, e_iu_dst, norm_i2u, E, NI);
    gather_kernel<<<(total_nodes + 7) / 8, 256>>>(feat_user, feat_item, NU, NI);

    const int ublocks = (NU + 127) / 128;
    const int iblocks = (NI + 127) / 128;
    gemm_mma_kernel<<<ublocks + iblocks, 256, SM_TOTAL>>>(
        feat_user, feat_item, b1, b2, out, NU, NI, ublocks);
}

// round 13
// speedup vs baseline: 1.3191x; 1.3191x over previous
#include <cuda_runtime.h>
#include <cuda_bf16.h>
#include <cstdint>
#include <math.h>

#define D 128
#define NU_MAX 100000
#define NI_MAX 50000
#define E_MAX  500000

// ---------------- scratch (device globals; no allocation allowed) ----------------
__device__ float4 g_agg_user4[(size_t)NU_MAX * D / 4];
__device__ float4 g_agg_item4[(size_t)NI_MAX * D / 4];
__device__ float  g_deg_user[NU_MAX];
__device__ float  g_deg_item[NI_MAX];
// pre-split, pre-swizzled bf16 weights: tiles m = {W1hi, W1lo, W2hi, W2lo}
__device__ unsigned char g_wt[4 * 32768];
// bucket-CSR build scratch: node index space = [0,NI) items, [NI, NI+NU) users
__device__ int   g_cnt[NU_MAX + NI_MAX];
__device__ int   g_base[NU_MAX + NI_MAX];
__device__ int   g_wr[NU_MAX + NI_MAX];
__device__ int   g_cursor[2];
__device__ uint2 g_epack_u2i[E_MAX];   // (src_user, norm_bits), grouped by dst item
__device__ uint2 g_epack_i2u[E_MAX];   // (src_item, norm_bits), grouped by dst user

// ---------------- helpers ----------------
__device__ __forceinline__ uint32_t smem_u32(const void* p) {
    uint32_t a;
    asm("{ .reg .u64 t; cvta.to.shared.u64 t, %1; cvt.u32.u64 %0, t; }" : "=r"(a) : "l"(p));
    return a;
}
__device__ __forceinline__ void ldmx4(uint32_t* r, uint32_t addr) {
    asm volatile("ldmatrix.sync.aligned.m8n8.x4.shared.b16 {%0,%1,%2,%3}, [%4];"
                 : "=r"(r[0]), "=r"(r[1]), "=r"(r[2]), "=r"(r[3]) : "r"(addr));
}
__device__ __forceinline__ void mma16816(float* c, const uint32_t* a, uint32_t b0, uint32_t b1) {
    asm volatile("mma.sync.aligned.m16n8k16.row.col.f32.bf16.bf16.f32 "
                 "{%0,%1,%2,%3}, {%4,%5,%6,%7}, {%8,%9}, {%0,%1,%2,%3};"
                 : "+f"(c[0]), "+f"(c[1]), "+f"(c[2]), "+f"(c[3])
                 : "r"(a[0]), "r"(a[1]), "r"(a[2]), "r"(a[3]), "r"(b0), "r"(b1));
}
__device__ __forceinline__ void pack_hl(const float* v, uint4* hi, uint4* lo) {
    uint32_t h[4], l[4];
    #pragma unroll
    for (int i = 0; i < 4; ++i) {
        float2 p = make_float2(v[2 * i], v[2 * i + 1]);
        __nv_bfloat162 hb = __float22bfloat162_rn(p);
        float2 r = make_float2(p.x - __bfloat162float(hb.x),
                               p.y - __bfloat162float(hb.y));
        __nv_bfloat162 lb = __float22bfloat162_rn(r);
        h[i] = *(uint32_t*)&hb;
        l[i] = *(uint32_t*)&lb;
    }
    *hi = make_uint4(h[0], h[1], h[2], h[3]);
    *lo = make_uint4(l[0], l[1], l[2], l[3]);
}

// ---------------- build phase ----------------
__global__ void zero_cnt_kernel(int total_nodes) {
    int i = blockIdx.x * blockDim.x + threadIdx.x;
    if (i < total_nodes) g_cnt[i] = 0;
    if (i < 2) g_cursor[i] = 0;
}

__global__ void count_kernel(const int* __restrict__ dst_u2i,
                             const int* __restrict__ dst_i2u, int E, int NI) {
    int i = blockIdx.x * blockDim.x + threadIdx.x;
    if (i < E) {
        atomicAdd(&g_cnt[__ldg(dst_u2i + i)], 1);
    } else if (i < 2 * E) {
        atomicAdd(&g_cnt[NI + __ldg(dst_i2u + (i - E))], 1);
    }
}

// Exclusive-offset assignment for one contiguous node range via block scan +
// ONE atomicAdd per block (bases need only be disjoint; block order is free).
template <int DIR>
__global__ void base_scan_kernel(int n, int node0) {
    int i = blockIdx.x * 256 + threadIdx.x;
    int lane = threadIdx.x & 31;
    int w = threadIdx.x >> 5;
    int c = (i < n) ? g_cnt[node0 + i] : 0;

    // inclusive warp scan
    int x = c;
    #pragma unroll
    for (int o = 1; o < 32; o <<= 1) {
        int t = __shfl_up_sync(0xffffffffu, x, o);
        if (lane >= o) x += t;
    }
    __shared__ int wsum[8];
    __shared__ int bbase;
    if (lane == 31) wsum[w] = x;
    __syncthreads();
    int wpre = 0;
    #pragma unroll
    for (int j = 0; j < 8; ++j) wpre += (j < w) ? wsum[j] : 0;
    int incl = x + wpre;
    if (threadIdx.x == 255) bbase = atomicAdd(&g_cursor[DIR], incl);
    __syncthreads();
    if (i < n) {
        int b = bbase + incl - c;
        g_base[node0 + i] = b;
        g_wr[node0 + i] = b;
    }
}

__global__ void fill_kernel(const int* __restrict__ src_u2i,
                            const int* __restrict__ dst_u2i,
                            const float* __restrict__ norm_u2i,
                            const int* __restrict__ src_i2u,
                            const int* __restrict__ dst_i2u,
                            const float* __restrict__ norm_i2u,
                            int E, int NI) {
    int i = blockIdx.x * blockDim.x + threadIdx.x;
    if (i < E) {
        int d = __ldg(dst_u2i + i);
        int p = atomicAdd(&g_wr[d], 1);
        if (p < E_MAX)
            g_epack_u2i[p] = make_uint2((uint32_t)__ldg(src_u2i + i),
                                        __float_as_uint(__ldg(norm_u2i + i)));
    } else if (i < 2 * E) {
        int j = i - E;
        int d = __ldg(dst_i2u + j);
        int p = atomicAdd(&g_wr[NI + d], 1);
        if (p < E_MAX)
            g_epack_i2u[p] = make_uint2((uint32_t)__ldg(src_i2u + j),
                                        __float_as_uint(__ldg(norm_i2u + j)));
    }
}

// ---------------- gather: one warp per dst node, no atomics, no pre-zero ----------------
__global__ void gather_kernel(const float* __restrict__ feat_user,
                              const float* __restrict__ feat_item,
                              int NU, int NI) {
    int gw = (blockIdx.x * blockDim.x + threadIdx.x) >> 5;
    int lane = threadIdx.x & 31;
    int total = NI + NU;
    if (gw >= total) return;

    const bool is_item = gw < NI;
    const int node = is_item ? gw : gw - NI;
    const float* fs = is_item ? feat_user : feat_item;
    const uint2* ep = is_item ? g_epack_u2i : g_epack_i2u;
    float4* agg = is_item ? (g_agg_item4 + (size_t)node * 32)
                          : (g_agg_user4 + (size_t)node * 32);
    float* degp = is_item ? (g_deg_item + node) : (g_deg_user + node);

    int e  = __ldg(g_base + gw);
    int e1 = e + __ldg(g_cnt + gw);

    float4 acc = make_float4(0.f, 0.f, 0.f, 0.f);
    float dg = 0.f;
    uint2 pk;
    float4 f;
    if (e < e1) {
        pk = __ldg(ep + e);
        f = __ldg(((const float4*)(fs + (size_t)pk.x * D)) + lane);
    }
    while (e < e1) {
        float w = __uint_as_float(pk.y);
        float4 cf = f;
        ++e;
        if (e < e1) {
            pk = __ldg(ep + e);
            f = __ldg(((const float4*)(fs + (size_t)pk.x * D)) + lane);
        }
        acc.x += w * cf.x;
        acc.y += w * cf.y;
        acc.z += w * cf.z;
        acc.w += w * cf.w;
        dg += w;
    }
    agg[lane] = acc;
    if (lane == 0) *degp = dg;
}

// ---------------- weight prep: bf16 hi/lo split, swizzled n-major tiles ----------------
__global__ void wprep_kernel(const float* __restrict__ W1, const float* __restrict__ W2) {
    int idx = blockIdx.x * blockDim.x + threadIdx.x;
    if (idx >= 2 * D * D) return;
    int w = idx >> 14;
    int k = (idx >> 7) & 127;
    int n = idx & 127;
    float v = __ldg((w ? W2 : W1) + k * D + n);
    __nv_bfloat16 hb = __float2bfloat16(v);
    __nv_bfloat16 lb = __float2bfloat16(v - __bfloat162float(hb));
    uint32_t off = (uint32_t)(n * 256 + (((k >> 3) ^ (n & 7)) * 16) + (k & 7) * 2);
    *(__nv_bfloat16*)(g_wt + (2 * w + 0) * 32768 + off) = hb;
    *(__nv_bfloat16*)(g_wt + (2 * w + 1) * 32768 + off) = lb;
}

// ---------------- mma.sync fused dual-GEMM + bias + LeakyReLU + row L2-normalize ----------------
#define SM_W_OFF 131072
#define SM_TOTAL (131072 + 65536)

__global__ __launch_bounds__(256, 1)
void gemm_mma_kernel(const float* __restrict__ feat_user,
                     const float* __restrict__ feat_item,
                     const float* __restrict__ b1v,
                     const float* __restrict__ b2v,
                     float* __restrict__ out,
                     int NU, int NI, int ublocks) {
    extern __shared__ char smem[];
    const uint32_t sbase = smem_u32(smem);
    const int tid = threadIdx.x;
    const int wid = tid >> 5;
    const int lane = tid & 31;

    const bool is_user = (int)blockIdx.x < ublocks;
    const int bx = is_user ? blockIdx.x : blockIdx.x - ublocks;
    const int Nrows = is_user ? NU : NI;
    const int row0 = bx * 128;
    const float* feat = is_user ? feat_user : feat_item;
    const float* agg  = is_user ? (const float*)g_agg_user4 : (const float*)g_agg_item4;
    const float* deg  = is_user ? g_deg_user : g_deg_item;
    float* outp = is_user ? out : out + (size_t)NU * D;

    // ---- stage A-operand tiles ----
    {
        int r = tid >> 1, khalf = tid & 1;
        int grow = row0 + r;
        bool valid = grow < Nrows;
        const float4* fp = (const float4*)(feat + (size_t)grow * D) + khalf * 16;
        const float4* ap = (const float4*)(agg  + (size_t)grow * D) + khalf * 16;
        const float4 z = make_float4(0.f, 0.f, 0.f, 0.f);
        uint32_t rbase = (uint32_t)(r * 256);
        int rs = r & 7;
        #pragma unroll
        for (int j = 0; j < 8; ++j) {
            float4 f0 = valid ? __ldg(fp + 2 * j)     : z;
            float4 f1 = valid ? __ldg(fp + 2 * j + 1) : z;
            float4 a0 = valid ? __ldg(ap + 2 * j)     : z;
            float4 a1 = valid ? __ldg(ap + 2 * j + 1) : z;
            float Av[8] = {f0.x + a0.x, f0.y + a0.y, f0.z + a0.z, f0.w + a0.w,
                           f1.x + a1.x, f1.y + a1.y, f1.z + a1.z, f1.w + a1.w};
            float Bv[8] = {f0.x * a0.x, f0.y * a0.y, f0.z * a0.z, f0.w * a0.w,
                           f1.x * a1.x, f1.y * a1.y, f1.z * a1.z, f1.w * a1.w};
            uint32_t off = rbase + (uint32_t)((((khalf * 8 + j) ^ rs)) * 16);
            uint4 hi, lo;
            pack_hl(Av, &hi, &lo);
            *(uint4*)(smem + 0 * 32768 + off) = hi;
            *(uint4*)(smem + 1 * 32768 + off) = lo;
            pack_hl(Bv, &hi, &lo);
            *(uint4*)(smem + 2 * 32768 + off) = hi;
            *(uint4*)(smem + 3 * 32768 + off) = lo;
        }
    }

    const int rg = wid & 3;
    const int cg = wid >> 2;
    const int lrow = lane & 15;
    const int lkh = lane >> 4;
    const int lswz = lrow & 7;

    float acc[2][2][4][4];
    #pragma unroll
    for (int h = 0; h < 2; ++h)
        #pragma unroll
        for (int mb = 0; mb < 2; ++mb)
            #pragma unroll
            for (int nb = 0; nb < 4; ++nb)
                #pragma unroll
                for (int e = 0; e < 4; ++e) acc[h][mb][nb][e] = 0.f;

    const int aidx[6] = {0, 0, 1, 2, 2, 3};
    const int widx[6] = {0, 1, 0, 2, 3, 2};

    const uint32_t rowA0 = (uint32_t)((rg * 32 + lrow) * 256);
    const uint32_t rowA1 = rowA0 + 16 * 256;
    const uint32_t rowB0 = (uint32_t)((cg * 32 + lrow) * 256);
    const uint32_t rowB1 = rowB0 + 16 * 256;

    for (int h = 0; h < 2; ++h) {
        __syncthreads();
        #pragma unroll
        for (int m = 0; m < 4; ++m) {
            const uint4* src = (const uint4*)(g_wt + m * 32768 + h * 16384);
            uint4* dst = (uint4*)(smem + SM_W_OFF + m * 16384);
            #pragma unroll
            for (int t = tid; t < 1024; t += 256) dst[t] = __ldg(src + t);
        }
        __syncthreads();

        #pragma unroll
        for (int p = 0; p < 6; ++p) {
            const uint32_t abase = sbase + (uint32_t)(aidx[p] * 32768);
            const uint32_t wbase = sbase + SM_W_OFF + (uint32_t)(widx[p] * 16384);
            #pragma unroll
            for (int ks = 0; ks < 8; ++ks) {
                uint32_t coff = (uint32_t)(((ks * 2 + lkh) ^ lswz) * 16);
                uint32_t a0r[4], a1r[4], b0r[4], b1r[4];
                ldmx4(a0r, abase + rowA0 + coff);
                ldmx4(a1r, abase + rowA1 + coff);
                ldmx4(b0r, wbase + rowB0 + coff);
                ldmx4(b1r, wbase + rowB1 + coff);
                #pragma unroll
                for (int mb = 0; mb < 2; ++mb) {
                    const uint32_t* a = mb ? a1r : a0r;
                    mma16816(acc[h][mb][0], a, b0r[0], b0r[2]);
                    mma16816(acc[h][mb][1], a, b0r[1], b0r[3]);
                    mma16816(acc[h][mb][2], a, b1r[0], b1r[2]);
                    mma16816(acc[h][mb][3], a, b1r[1], b1r[3]);
                }
            }
        }
    }
    __syncthreads();

    // ---- epilogue ----
    const int rl = lane >> 2;
    float dg[2][2], ss[2][2];
    #pragma unroll
    for (int mb = 0; mb < 2; ++mb)
        #pragma unroll
        for (int rh = 0; rh < 2; ++rh) {
            int grow = row0 + rg * 32 + mb * 16 + rh * 8 + rl;
            dg[mb][rh] = (grow < Nrows) ? __ldg(deg + grow) : 0.f;
            ss[mb][rh] = 0.f;
        }

    #pragma unroll
    for (int h = 0; h < 2; ++h)
        #pragma unroll
        for (int nb = 0; nb < 4; ++nb) {
            int col = h * 64 + cg * 32 + nb * 8 + (lane & 3) * 2;
            float2 bb1 = __ldg((const float2*)(b1v + col));
            float2 bb2 = __ldg((const float2*)(b2v + col));
            #pragma unroll
            for (int mb = 0; mb < 2; ++mb)
                #pragma unroll
                for (int rh = 0; rh < 2; ++rh) {
                    float d = dg[mb][rh];
                    float* c = acc[h][mb][nb] + rh * 2;
                    float h0 = c[0] + (1.f + d) * bb1.x + d * bb2.x;
                    float h1 = c[1] + (1.f + d) * bb1.y + d * bb2.y;
                    h0 = (h0 > 0.f) ? h0 : 0.2f * h0;
                    h1 = (h1 > 0.f) ? h1 : 0.2f * h1;
                    c[0] = h0; c[1] = h1;
                    ss[mb][rh] += h0 * h0 + h1 * h1;
                }
        }
    #pragma unroll
    for (int off = 1; off <= 2; off <<= 1)
        #pragma unroll
        for (int mb = 0; mb < 2; ++mb)
            #pragma unroll
            for (int rh = 0; rh < 2; ++rh)
                ss[mb][rh] += __shfl_xor_sync(0xffffffffu, ss[mb][rh], off);

    float* part = (float*)smem;
    if ((lane & 3) == 0) {
        #pragma unroll
        for (int mb = 0; mb < 2; ++mb)
            #pragma unroll
            for (int rh = 0; rh < 2; ++rh)
                part[cg * 128 + rg * 32 + mb * 16 + rh * 8 + rl] = ss[mb][rh];
    }
    __syncthreads();

    #pragma unroll
    for (int mb = 0; mb < 2; ++mb)
        #pragma unroll
        for (int rh = 0; rh < 2; ++rh) {
            int lrow128 = rg * 32 + mb * 16 + rh * 8 + rl;
            int grow = row0 + lrow128;
            float tot = ss[mb][rh] + part[(1 ^ cg) * 128 + lrow128];
            float inv = 1.f / fmaxf(sqrtf(tot), 1e-12f);
            if (grow < Nrows) {
                #pragma unroll
                for (int h = 0; h < 2; ++h)
                    #pragma unroll
                    for (int nb = 0; nb < 4; ++nb) {
                        int col = h * 64 + cg * 32 + nb * 8 + (lane & 3) * 2;
                        float* c = acc[h][mb][nb] + rh * 2;
                        *(float2*)(outp + (size_t)grow * D + col) =
                            make_float2(c[0] * inv, c[1] * inv);
                    }
            }
        }
}

// ---------------- launch ----------------
extern "C" void kernel_launch(void* const* d_in, const int* in_sizes, int n_in,
                              void* d_out, int out_size) {
    const float* feat_user = (const float*)d_in[0];
    const float* feat_item = (const float*)d_in[1];
    const float* W1        = (const float*)d_in[2];
    const float* b1        = (const float*)d_in[3];
    const float* W2        = (const float*)d_in[4];
    const float* b2        = (const float*)d_in[5];
    const float* norm_u2i  = (const float*)d_in[6];
    const float* norm_i2u  = (const float*)d_in[7];
    const int*   e_ui_src  = (const int*)d_in[8];
    const int*   e_ui_dst  = (const int*)d_in[9];
    const int*   e_iu_src  = (const int*)d_in[10];
    const int*   e_iu_dst  = (const int*)d_in[11];
    float* out = (float*)d_out;

    const int NU = in_sizes[0] / D;
    const int NI = in_sizes[1] / D;
    const int E  = in_sizes[8];
    const int total_nodes = NU + NI;

    cudaFuncSetAttribute((const void*)gemm_mma_kernel,
                         cudaFuncAttributeMaxDynamicSharedMemorySize, SM_TOTAL);

    zero_cnt_kernel<<<(total_nodes + 255) / 256, 256>>>(total_nodes);
    wprep_kernel<<<(2 * D * D + 255) / 256, 256>>>(W1, W2);
    count_kernel<<<(2 * E + 255) / 256, 256>>>(e_ui_dst, e_iu_dst, E, NI);
    base_scan_kernel<0><<<(NI + 255) / 256, 256>>>(NI, 0);     // items
    base_scan_kernel<1><<<(NU + 255) / 256, 256>>>(NU, NI);    // users
    fill_kernel<<<(2 * E + 255) / 256, 256>>>(e_ui_src, e_ui_dst, norm_u2i,
                                              e_iu_src, e_iu_dst, norm_i2u, E, NI);
    gather_kernel<<<(total_nodes + 7) / 8, 256>>>(feat_user, feat_item, NU, NI);

    const int ublocks = (NU + 127) / 128;
    const int iblocks = (NI + 127) / 128;
    gemm_mma_kernel<<<ublocks + iblocks, 256, SM_TOTAL>>>(
        feat_user, feat_item, b1, b2, out, NU, NI, ublocks);
}